// round 1
// baseline (speedup 1.0000x reference)
#include <cuda_runtime.h>
#include <cuda_bf16.h>
#include <cstdint>

// Problem constants (fixed shapes from reference)
#define BATCH 8
#define C_DIM 512
#define N_DIM 4096
#define EPSV  1e-6f

// ---------------- scratch (device globals; no allocations allowed) ----------
__device__ __nv_bfloat16 g_xbt[(size_t)BATCH * N_DIM * C_DIM];        // x^T  bf16 [b][n][c]
__device__ __nv_bfloat16 g_wb[3ULL * C_DIM * C_DIM];                  // Wq|Wk|Wv bf16
__device__ float         g_qkv[3ULL * BATCH * C_DIM * N_DIM];         // Q,K,V fp32
__device__ __nv_bfloat16 g_qn[(size_t)BATCH * C_DIM * N_DIM];         // normalized Q bf16
__device__ __nv_bfloat16 g_kn[(size_t)BATCH * C_DIM * N_DIM];         // normalized K bf16
__device__ __nv_bfloat16 g_vt[(size_t)BATCH * N_DIM * C_DIM];         // V^T bf16 [b][n][d]
__device__ float         g_m[(size_t)BATCH * C_DIM * C_DIM];          // M fp32
__device__ __nv_bfloat16 g_mb[(size_t)BATCH * C_DIM * C_DIM];         // M bf16 (final weights)

// ---------------- transpose + fp32->bf16 convert -----------------------------
// src: [b][R=C_DIM][N_DIM] fp32 ; dst: [b][N_DIM][C_DIM] bf16 (transposed)
__global__ void transpose_cvt(const float* __restrict__ src, __nv_bfloat16* __restrict__ dst) {
    __shared__ float tile[32][33];
    int b = blockIdx.z;
    const float* s = src + (size_t)b * C_DIM * N_DIM;
    __nv_bfloat16* d = dst + (size_t)b * C_DIM * N_DIM;
    int n0 = blockIdx.x * 32, c0 = blockIdx.y * 32;
#pragma unroll
    for (int i = 0; i < 32; i += 8)
        tile[threadIdx.y + i][threadIdx.x] =
            s[(size_t)(c0 + threadIdx.y + i) * N_DIM + n0 + threadIdx.x];
    __syncthreads();
#pragma unroll
    for (int i = 0; i < 32; i += 8)
        d[(size_t)(n0 + threadIdx.y + i) * C_DIM + c0 + threadIdx.x] =
            __float2bfloat16(tile[threadIdx.x][threadIdx.y + i]);
}

// ---------------- convert the three 512x512 weight matrices ------------------
__global__ void cvt_w(const float* __restrict__ wq, const float* __restrict__ wk,
                      const float* __restrict__ wv) {
    int i = blockIdx.x * blockDim.x + threadIdx.x;
    if (i < C_DIM * C_DIM) {
        g_wb[i]                      = __float2bfloat16(wq[i]);
        g_wb[i + C_DIM * C_DIM]     = __float2bfloat16(wk[i]);
        g_wb[i + 2 * C_DIM * C_DIM] = __float2bfloat16(wv[i]);
    }
}

// ---------------- generic bf16 NT GEMM (mma.sync m16n8k16, fp32 accum) -------
// C[M,N] = sum_k A[m][k] * B[n][k], A ld=K, B ld=K, C ld=N.
// EPI==0 : plain fp32 store.  EPI==1 : C = X + gamma[0]*acc (residual epilogue)
#define BM 128
#define BN 128
#define BKT 32
#define SPAD 8

template <int EPI>
__global__ __launch_bounds__(256) void gemm_nt(
    const __nv_bfloat16* __restrict__ A, const __nv_bfloat16* __restrict__ B,
    float* __restrict__ C, int M, int N, int K,
    long long strA, long long strB, long long strC,
    const float* __restrict__ X, const float* __restrict__ gamma)
{
    __shared__ __nv_bfloat16 shA[BM][BKT + SPAD];
    __shared__ __nv_bfloat16 shB[BN][BKT + SPAD];

    int bz = blockIdx.z;
    A += (size_t)bz * strA;
    B += (size_t)bz * strB;
    C += (size_t)bz * strC;

    int m0 = blockIdx.y * BM, n0 = blockIdx.x * BN;
    int tid = threadIdx.x;
    int lane = tid & 31, w = tid >> 5;
    int wm = (w & 1) * 64;   // warp row offset (2 warps in m)
    int wn = (w >> 1) * 32;  // warp col offset (4 warps in n)
    int r = lane >> 2, q = lane & 3;

    float acc[4][4][4];
#pragma unroll
    for (int mi = 0; mi < 4; mi++)
#pragma unroll
        for (int ni = 0; ni < 4; ni++)
#pragma unroll
            for (int t = 0; t < 4; t++) acc[mi][ni][t] = 0.f;

    int lrow = tid >> 2;           // 0..63
    int lcol = (tid & 3) * 8;      // 0,8,16,24

    for (int kt = 0; kt < K; kt += BKT) {
        uint4 va0 = *(const uint4*)(A + (size_t)(m0 + lrow) * K + kt + lcol);
        uint4 va1 = *(const uint4*)(A + (size_t)(m0 + lrow + 64) * K + kt + lcol);
        uint4 vb0 = *(const uint4*)(B + (size_t)(n0 + lrow) * K + kt + lcol);
        uint4 vb1 = *(const uint4*)(B + (size_t)(n0 + lrow + 64) * K + kt + lcol);
        __syncthreads();
        *(uint4*)(&shA[lrow][lcol])      = va0;
        *(uint4*)(&shA[lrow + 64][lcol]) = va1;
        *(uint4*)(&shB[lrow][lcol])      = vb0;
        *(uint4*)(&shB[lrow + 64][lcol]) = vb1;
        __syncthreads();

#pragma unroll
        for (int ks = 0; ks < 2; ks++) {
            int kb = ks * 16;
            uint32_t ra[4][4], rb[4][2];
#pragma unroll
            for (int mi = 0; mi < 4; mi++) {
                int mr = wm + mi * 16 + r;
                ra[mi][0] = *(const uint32_t*)&shA[mr][kb + 2 * q];
                ra[mi][1] = *(const uint32_t*)&shA[mr + 8][kb + 2 * q];
                ra[mi][2] = *(const uint32_t*)&shA[mr][kb + 2 * q + 8];
                ra[mi][3] = *(const uint32_t*)&shA[mr + 8][kb + 2 * q + 8];
            }
#pragma unroll
            for (int ni = 0; ni < 4; ni++) {
                int nr = wn + ni * 8 + r;
                rb[ni][0] = *(const uint32_t*)&shB[nr][kb + 2 * q];
                rb[ni][1] = *(const uint32_t*)&shB[nr][kb + 2 * q + 8];
            }
#pragma unroll
            for (int mi = 0; mi < 4; mi++)
#pragma unroll
                for (int ni = 0; ni < 4; ni++) {
                    asm volatile(
                        "mma.sync.aligned.m16n8k16.row.col.f32.bf16.bf16.f32 "
                        "{%0,%1,%2,%3}, {%4,%5,%6,%7}, {%8,%9}, {%0,%1,%2,%3};\n"
                        : "+f"(acc[mi][ni][0]), "+f"(acc[mi][ni][1]),
                          "+f"(acc[mi][ni][2]), "+f"(acc[mi][ni][3])
                        : "r"(ra[mi][0]), "r"(ra[mi][1]), "r"(ra[mi][2]), "r"(ra[mi][3]),
                          "r"(rb[ni][0]), "r"(rb[ni][1]));
                }
        }
    }

    float g = 0.f;
    const float* xb = nullptr;
    if (EPI == 1) {
        g = gamma[0];
        xb = X + (size_t)bz * strC;
    }
#pragma unroll
    for (int mi = 0; mi < 4; mi++)
#pragma unroll
        for (int ni = 0; ni < 4; ni++) {
            int row = m0 + wm + mi * 16 + r;
            int col = n0 + wn + ni * 8 + 2 * q;
            size_t o0 = (size_t)row * N + col;
            size_t o1 = (size_t)(row + 8) * N + col;
            if (EPI == 0) {
                *(float2*)&C[o0] = make_float2(acc[mi][ni][0], acc[mi][ni][1]);
                *(float2*)&C[o1] = make_float2(acc[mi][ni][2], acc[mi][ni][3]);
            } else {
                float2 x0 = *(const float2*)&xb[o0];
                float2 x1 = *(const float2*)&xb[o1];
                *(float2*)&C[o0] = make_float2(x0.x + g * acc[mi][ni][0],
                                               x0.y + g * acc[mi][ni][1]);
                *(float2*)&C[o1] = make_float2(x1.x + g * acc[mi][ni][2],
                                               x1.y + g * acc[mi][ni][3]);
            }
        }
}

// ---------------- L2 row-normalize (over N) + convert to bf16 ----------------
// grid (C_DIM, BATCH, 2): z=0 -> Q, z=1 -> K. 256 threads.
__global__ __launch_bounds__(256) void l2norm_cvt() {
    int c = blockIdx.x, b = blockIdx.y, j = blockIdx.z;
    const float* src = g_qkv + ((size_t)j * BATCH + b) * C_DIM * N_DIM + (size_t)c * N_DIM;
    __nv_bfloat16* dst = (j ? g_kn : g_qn) + ((size_t)b * C_DIM + c) * N_DIM;

    float s = 0.f;
    for (int i = threadIdx.x; i < N_DIM / 4; i += 256) {
        float4 v = ((const float4*)src)[i];
        s += v.x * v.x + v.y * v.y + v.z * v.z + v.w * v.w;
    }
    __shared__ float red[8];
#pragma unroll
    for (int o = 16; o; o >>= 1) s += __shfl_xor_sync(0xffffffffu, s, o);
    if ((threadIdx.x & 31) == 0) red[threadIdx.x >> 5] = s;
    __syncthreads();
    if (threadIdx.x < 8) {
        float t = red[threadIdx.x];
#pragma unroll
        for (int o = 4; o; o >>= 1) t += __shfl_xor_sync(0xffu, t, o);
        if (threadIdx.x == 0) red[0] = t;
    }
    __syncthreads();
    float inv = rsqrtf(red[0]);
    for (int i = threadIdx.x; i < N_DIM / 4; i += 256) {
        float4 v = ((const float4*)src)[i];
        ((__nv_bfloat162*)dst)[2 * i]     = __floats2bfloat162_rn(v.x * inv, v.y * inv);
        ((__nv_bfloat162*)dst)[2 * i + 1] = __floats2bfloat162_rn(v.z * inv, v.w * inv);
    }
}

// ---------------- block reductions (512 threads) -----------------------------
template <bool ISMAX>
__device__ __forceinline__ float blk_reduce(float v) {
    __shared__ float sm[16];
#pragma unroll
    for (int o = 16; o; o >>= 1) {
        float t = __shfl_xor_sync(0xffffffffu, v, o);
        v = ISMAX ? fmaxf(v, t) : v + t;
    }
    if ((threadIdx.x & 31) == 0) sm[threadIdx.x >> 5] = v;
    __syncthreads();
    if (threadIdx.x < 32) {
        v = (threadIdx.x < 16) ? sm[threadIdx.x] : (ISMAX ? -1e30f : 0.f);
#pragma unroll
        for (int o = 16; o; o >>= 1) {
            float t = __shfl_xor_sync(0xffffffffu, v, o);
            v = ISMAX ? fmaxf(v, t) : v + t;
        }
        if (threadIdx.x == 0) sm[0] = v;
    }
    __syncthreads();
    v = sm[0];
    __syncthreads();
    return v;
}

// ---------------- column ops: cosine-dist normalize + softmax over c ---------
// grid (C_DIM columns d, BATCH), 512 threads = one per row c. In-place on g_m.
__global__ __launch_bounds__(512) void col_ops() {
    int d = blockIdx.x, b = blockIdx.y;
    float* Mp = g_m + (size_t)b * C_DIM * C_DIM;
    int c = threadIdx.x;
    float m = Mp[(size_t)c * C_DIM + d];
    float t = 1.f - m;                       // cosine distance
    float tmax = blk_reduce<true>(t);
    t = t / (tmax + EPSV);
    float u = 1.f - t * 4.f;                 // 1 - t / 0.25
    float umax = blk_reduce<true>(u);
    float e = expf(u - umax);
    float esum = blk_reduce<false>(e);
    Mp[(size_t)c * C_DIM + d] = e / esum;
}

// ---------------- row ops: L1 normalize over d, convert to bf16 --------------
// grid (C_DIM rows c, BATCH), 512 threads = one per column d.
__global__ __launch_bounds__(512) void row_ops() {
    int c = blockIdx.x, b = blockIdx.y;
    const float* Mp = g_m + (size_t)b * C_DIM * C_DIM + (size_t)c * C_DIM;
    float v = Mp[threadIdx.x];
    float s = blk_reduce<false>(v);
    g_mb[(size_t)b * C_DIM * C_DIM + (size_t)c * C_DIM + threadIdx.x] =
        __float2bfloat16(v / (s + EPSV));
}

// ---------------- launch --------------------------------------------------
extern "C" void kernel_launch(void* const* d_in, const int* in_sizes, int n_in,
                              void* d_out, int out_size) {
    const float* x  = (const float*)d_in[0];
    const float* wq = (const float*)d_in[1];
    const float* wk = (const float*)d_in[2];
    const float* wv = (const float*)d_in[3];
    const float* gamma = (const float*)d_in[4];
    float* out = (float*)d_out;

    void *p_xbt, *p_wb, *p_qkv, *p_qn, *p_kn, *p_vt, *p_m, *p_mb;
    cudaGetSymbolAddress(&p_xbt, g_xbt);
    cudaGetSymbolAddress(&p_wb,  g_wb);
    cudaGetSymbolAddress(&p_qkv, g_qkv);
    cudaGetSymbolAddress(&p_qn,  g_qn);
    cudaGetSymbolAddress(&p_kn,  g_kn);
    cudaGetSymbolAddress(&p_vt,  g_vt);
    cudaGetSymbolAddress(&p_m,   g_m);
    cudaGetSymbolAddress(&p_mb,  g_mb);

    const long long perBatchCN = (long long)C_DIM * N_DIM;   // 2,097,152
    const long long perBatchCC = (long long)C_DIM * C_DIM;   // 262,144

    dim3 tb(32, 8);
    // 1) x -> x^T bf16
    transpose_cvt<<<dim3(N_DIM / 32, C_DIM / 32, BATCH), tb>>>(x, (__nv_bfloat16*)p_xbt);
    // 2) weights -> bf16
    cvt_w<<<(C_DIM * C_DIM + 255) / 256, 256>>>(wq, wk, wv);
    // 3) Q,K,V = W @ x   (A=W [512x512], B=x^T [4096x512], C fp32 [512x4096])
    for (int j = 0; j < 3; j++) {
        gemm_nt<0><<<dim3(N_DIM / BN, C_DIM / BM, BATCH), 256>>>(
            (const __nv_bfloat16*)p_wb + (size_t)j * C_DIM * C_DIM,
            (const __nv_bfloat16*)p_xbt,
            (float*)p_qkv + (size_t)j * BATCH * C_DIM * N_DIM,
            C_DIM, N_DIM, C_DIM,
            0LL, perBatchCN, perBatchCN, nullptr, nullptr);
    }
    // 4) L2-normalize Q,K rows -> bf16
    l2norm_cvt<<<dim3(C_DIM, BATCH, 2), 256>>>();
    // 5) V -> V^T bf16
    transpose_cvt<<<dim3(N_DIM / 32, C_DIM / 32, BATCH), tb>>>(
        (const float*)p_qkv + 2ULL * BATCH * C_DIM * N_DIM, (__nv_bfloat16*)p_vt);
    // 6) M = Qn @ Kn^T   (K = 4096)
    gemm_nt<0><<<dim3(C_DIM / BN, C_DIM / BM, BATCH), 256>>>(
        (const __nv_bfloat16*)p_qn, (const __nv_bfloat16*)p_kn, (float*)p_m,
        C_DIM, C_DIM, N_DIM,
        perBatchCN, perBatchCN, perBatchCC, nullptr, nullptr);
    // 7) column-wise cosine-dist normalize + softmax
    col_ops<<<dim3(C_DIM, BATCH), 512>>>();
    // 8) row-wise L1 normalize -> bf16
    row_ops<<<dim3(C_DIM, BATCH), 512>>>();
    // 9) out = x + gamma * (M @ V)
    gemm_nt<1><<<dim3(N_DIM / BN, C_DIM / BM, BATCH), 256>>>(
        (const __nv_bfloat16*)p_mb, (const __nv_bfloat16*)p_vt, out,
        C_DIM, N_DIM, C_DIM,
        perBatchCC, perBatchCN, perBatchCN, x, gamma);
}

// round 2
// speedup vs baseline: 1.7588x; 1.7588x over previous
#include <cuda_runtime.h>
#include <cuda_bf16.h>
#include <cstdint>

#define BATCH 8
#define C_DIM 512
#define N_DIM 4096
#define EPSV  1e-6f
#define SKM   4          // split-K factor for the M = Q K^T GEMM

// ---------------- scratch (device globals) -----------------------------------
__device__ __nv_bfloat16 g_xbt[(size_t)BATCH * N_DIM * C_DIM];      // x^T bf16 [b][n][c]
__device__ __nv_bfloat16 g_wb[3ULL * C_DIM * C_DIM];                // Wq|Wk|Wv bf16
__device__ float         g_qk[(size_t)BATCH * 2 * C_DIM * N_DIM];   // Q,K fp32 [b][1024][4096]
__device__ __nv_bfloat16 g_qn[(size_t)BATCH * C_DIM * N_DIM];       // normalized Q
__device__ __nv_bfloat16 g_kn[(size_t)BATCH * C_DIM * N_DIM];       // normalized K
__device__ __nv_bfloat16 g_vt[(size_t)BATCH * N_DIM * C_DIM];       // V^T bf16 [b][n][d]
__device__ float         g_mpart[(size_t)SKM * BATCH * C_DIM * C_DIM]; // split-K partials
__device__ float         g_m[(size_t)BATCH * C_DIM * C_DIM];        // M fp32
__device__ __nv_bfloat16 g_mb[(size_t)BATCH * C_DIM * C_DIM];       // M bf16

// ---------------- transpose + fp32->bf16 convert -----------------------------
__global__ void transpose_cvt(const float* __restrict__ src, __nv_bfloat16* __restrict__ dst) {
    __shared__ float tile[32][33];
    int b = blockIdx.z;
    const float* s = src + (size_t)b * C_DIM * N_DIM;
    __nv_bfloat16* d = dst + (size_t)b * C_DIM * N_DIM;
    int n0 = blockIdx.x * 32, c0 = blockIdx.y * 32;
#pragma unroll
    for (int i = 0; i < 32; i += 8)
        tile[threadIdx.y + i][threadIdx.x] =
            s[(size_t)(c0 + threadIdx.y + i) * N_DIM + n0 + threadIdx.x];
    __syncthreads();
#pragma unroll
    for (int i = 0; i < 32; i += 8)
        d[(size_t)(n0 + threadIdx.y + i) * C_DIM + c0 + threadIdx.x] =
            __float2bfloat16(tile[threadIdx.x][threadIdx.y + i]);
}

__global__ void cvt_w(const float* __restrict__ wq, const float* __restrict__ wk,
                      const float* __restrict__ wv) {
    int i = blockIdx.x * blockDim.x + threadIdx.x;
    if (i < C_DIM * C_DIM) {
        g_wb[i]                     = __float2bfloat16(wq[i]);
        g_wb[i + C_DIM * C_DIM]     = __float2bfloat16(wk[i]);
        g_wb[i + 2 * C_DIM * C_DIM] = __float2bfloat16(wv[i]);
    }
}

// ---------------- helpers -----------------------------------------------------
__device__ __forceinline__ uint32_t smem_u32(const void* p) {
    return (uint32_t)__cvta_generic_to_shared(p);
}
__device__ __forceinline__ void cpa16(uint32_t d, const void* s) {
    asm volatile("cp.async.cg.shared.global [%0], [%1], 16;\n" :: "r"(d), "l"(s));
}
__device__ __forceinline__ void ldsm4(uint32_t& r0, uint32_t& r1, uint32_t& r2, uint32_t& r3,
                                      uint32_t a) {
    asm volatile("ldmatrix.sync.aligned.m8n8.x4.shared.b16 {%0,%1,%2,%3}, [%4];\n"
                 : "=r"(r0), "=r"(r1), "=r"(r2), "=r"(r3) : "r"(a));
}
__device__ __forceinline__ void mma16816(float* c, const uint32_t* a, uint32_t b0, uint32_t b1) {
    asm volatile("mma.sync.aligned.m16n8k16.row.col.f32.bf16.bf16.f32 "
                 "{%0,%1,%2,%3}, {%4,%5,%6,%7}, {%8,%9}, {%0,%1,%2,%3};\n"
                 : "+f"(c[0]), "+f"(c[1]), "+f"(c[2]), "+f"(c[3])
                 : "r"(a[0]), "r"(a[1]), "r"(a[2]), "r"(a[3]), "r"(b0), "r"(b1));
}

// ---------------- bf16 NT GEMM, cp.async double-buffered, ldmatrix -----------
// C[M,N] = sum_k A[m][k]*B[n][k].  M,N multiples of 128, K multiple of 64.
// EPI 0: fp32 store.  EPI 1: C = X + gamma*acc (fp32).  EPI 3: bf16 store.
#define BM 128
#define BN 128
#define BK 64
#define STG_BYTES 32768   // (128+128)*64*2 per stage

template <int EPI>
__global__ __launch_bounds__(256, 2) void gemm_nt(
    const __nv_bfloat16* __restrict__ A, const __nv_bfloat16* __restrict__ B,
    void* __restrict__ Cv, int N, int K, int lda, int ldb,
    long long strA, long long strB, long long strC, int SK, long long kcStr,
    const float* __restrict__ X, const float* __restrict__ gamma)
{
    extern __shared__ char smraw[];
    int bz = blockIdx.z;
    int b = bz / SK, kc = bz - b * SK;
    A += (size_t)b * strA + (size_t)kc * K;
    B += (size_t)b * strB + (size_t)kc * K;

    int m0 = blockIdx.y * BM, n0 = blockIdx.x * BN;
    int tid = threadIdx.x;
    int lane = tid & 31, w = tid >> 5;
    int wm = (w & 1) * 64;
    int wn = (w >> 1) * 32;
    int r = lane >> 2, q = lane & 3;

    uint32_t sbase = smem_u32(smraw);
    // stage s: A tile at sbase + s*STG_BYTES, B tile at +16384

    float acc[4][4][4];
#pragma unroll
    for (int mi = 0; mi < 4; mi++)
#pragma unroll
        for (int ni = 0; ni < 4; ni++)
#pragma unroll
            for (int t = 0; t < 4; t++) acc[mi][ni][t] = 0.f;

    int lr = tid >> 3;     // 0..31
    int lc = tid & 7;      // 16B chunk index 0..7

    auto issue = [&](int kt, int s) {
        uint32_t sA = sbase + s * STG_BYTES;
        uint32_t sB = sA + 16384;
        const __nv_bfloat16* Ag = A + (size_t)kt * BK;
        const __nv_bfloat16* Bg = B + (size_t)kt * BK;
#pragma unroll
        for (int p = 0; p < 4; p++) {
            int row = lr + p * 32;
            uint32_t off = row * 128 + ((lc ^ (row & 7)) << 4);
            cpa16(sA + off, Ag + (size_t)(m0 + row) * lda + lc * 8);
            cpa16(sB + off, Bg + (size_t)(n0 + row) * ldb + lc * 8);
        }
    };

    int nk = K / BK;
    issue(0, 0);
    asm volatile("cp.async.commit_group;\n");

    for (int kt = 0; kt < nk; kt++) {
        int cur = kt & 1;
        if (kt + 1 < nk) {
            issue(kt + 1, cur ^ 1);
            asm volatile("cp.async.commit_group;\n");
            asm volatile("cp.async.wait_group 1;\n");
        } else {
            asm volatile("cp.async.wait_group 0;\n");
        }
        __syncthreads();

        uint32_t sA = sbase + cur * STG_BYTES;
        uint32_t sB = sA + 16384;
#pragma unroll
        for (int ks = 0; ks < BK / 16; ks++) {
            uint32_t ra[4][4];
            int kca = ks * 2 + (lane >> 4);
#pragma unroll
            for (int mi = 0; mi < 4; mi++) {
                int row = wm + mi * 16 + (lane & 15);
                uint32_t ad = sA + row * 128 + ((kca ^ (row & 7)) << 4);
                ldsm4(ra[mi][0], ra[mi][1], ra[mi][2], ra[mi][3], ad);
            }
            uint32_t rb[2][4];
            int kcb = ks * 2 + ((lane >> 3) & 1);
            int rbo = (lane & 7) + ((lane >> 4) << 3);
#pragma unroll
            for (int nj = 0; nj < 2; nj++) {
                int row = wn + nj * 16 + rbo;
                uint32_t bd = sB + row * 128 + ((kcb ^ (row & 7)) << 4);
                ldsm4(rb[nj][0], rb[nj][1], rb[nj][2], rb[nj][3], bd);
            }
#pragma unroll
            for (int mi = 0; mi < 4; mi++)
#pragma unroll
                for (int nj = 0; nj < 2; nj++) {
                    mma16816(acc[mi][2 * nj],     ra[mi], rb[nj][0], rb[nj][1]);
                    mma16816(acc[mi][2 * nj + 1], ra[mi], rb[nj][2], rb[nj][3]);
                }
        }
        __syncthreads();
    }

    // ---------------- epilogue ----------------
    if (EPI == 3) {
        __nv_bfloat16* C = (__nv_bfloat16*)Cv + (size_t)b * strC;
#pragma unroll
        for (int mi = 0; mi < 4; mi++)
#pragma unroll
            for (int ni = 0; ni < 4; ni++) {
                int row = m0 + wm + mi * 16 + r;
                int col = n0 + wn + ni * 8 + 2 * q;
                *(__nv_bfloat162*)&C[(size_t)row * N + col] =
                    __floats2bfloat162_rn(acc[mi][ni][0], acc[mi][ni][1]);
                *(__nv_bfloat162*)&C[(size_t)(row + 8) * N + col] =
                    __floats2bfloat162_rn(acc[mi][ni][2], acc[mi][ni][3]);
            }
    } else {
        float* C = (float*)Cv + (size_t)b * strC + (size_t)kc * kcStr;
        float g = 0.f;
        const float* xb = nullptr;
        if (EPI == 1) { g = gamma[0]; xb = X + (size_t)b * strC; }
#pragma unroll
        for (int mi = 0; mi < 4; mi++)
#pragma unroll
            for (int ni = 0; ni < 4; ni++) {
                int row = m0 + wm + mi * 16 + r;
                int col = n0 + wn + ni * 8 + 2 * q;
                size_t o0 = (size_t)row * N + col;
                size_t o1 = (size_t)(row + 8) * N + col;
                if (EPI == 0) {
                    *(float2*)&C[o0] = make_float2(acc[mi][ni][0], acc[mi][ni][1]);
                    *(float2*)&C[o1] = make_float2(acc[mi][ni][2], acc[mi][ni][3]);
                } else {
                    float2 x0 = *(const float2*)&xb[o0];
                    float2 x1 = *(const float2*)&xb[o1];
                    *(float2*)&C[o0] = make_float2(x0.x + g * acc[mi][ni][0],
                                                   x0.y + g * acc[mi][ni][1]);
                    *(float2*)&C[o1] = make_float2(x1.x + g * acc[mi][ni][2],
                                                   x1.y + g * acc[mi][ni][3]);
                }
            }
    }
}

// ---------------- L2 row-normalize (over N) + convert to bf16 ----------------
// grid (1024, BATCH): rows 0..511 -> Q, 512..1023 -> K
__global__ __launch_bounds__(256) void l2norm_cvt() {
    int rrow = blockIdx.x, b = blockIdx.y;
    const float* src = g_qk + ((size_t)b * 2 * C_DIM + rrow) * N_DIM;
    __nv_bfloat16* dst = (rrow < C_DIM ? g_qn : g_kn) +
                         ((size_t)b * C_DIM + (rrow & (C_DIM - 1))) * N_DIM;
    float s = 0.f;
    for (int i = threadIdx.x; i < N_DIM / 4; i += 256) {
        float4 v = ((const float4*)src)[i];
        s += v.x * v.x + v.y * v.y + v.z * v.z + v.w * v.w;
    }
    __shared__ float red[8];
#pragma unroll
    for (int o = 16; o; o >>= 1) s += __shfl_xor_sync(0xffffffffu, s, o);
    if ((threadIdx.x & 31) == 0) red[threadIdx.x >> 5] = s;
    __syncthreads();
    if (threadIdx.x < 8) {
        float t = red[threadIdx.x];
#pragma unroll
        for (int o = 4; o; o >>= 1) t += __shfl_xor_sync(0xffu, t, o);
        if (threadIdx.x == 0) red[0] = t;
    }
    __syncthreads();
    float inv = rsqrtf(red[0]);
    for (int i = threadIdx.x; i < N_DIM / 4; i += 256) {
        float4 v = ((const float4*)src)[i];
        ((__nv_bfloat162*)dst)[2 * i]     = __floats2bfloat162_rn(v.x * inv, v.y * inv);
        ((__nv_bfloat162*)dst)[2 * i + 1] = __floats2bfloat162_rn(v.z * inv, v.w * inv);
    }
}

// ---------------- col ops: sum split-K partials, cosine-dist norm, softmax ----
// block (32 d, 16 c-strides), grid (C_DIM/32, BATCH). Fully coalesced.
__global__ __launch_bounds__(512) void col_ops() {
    int b = blockIdx.y;
    int tx = threadIdx.x, ty = threadIdx.y;
    int d = blockIdx.x * 32 + tx;
    const size_t cc = (size_t)C_DIM * C_DIM;
    float* Mo = g_m + (size_t)b * cc;
    const float* P = g_mpart + (size_t)b * cc;
    const size_t ks = (size_t)BATCH * cc;

    float mmax = -1e30f, mmin = 1e30f;
    for (int c = ty; c < C_DIM; c += 16) {
        size_t o = (size_t)c * C_DIM + d;
        float m = P[o] + P[o + ks] + P[o + 2 * ks] + P[o + 3 * ks];
        Mo[o] = m;
        mmax = fmaxf(mmax, m);
        mmin = fminf(mmin, m);
    }
    __shared__ float s1[16][33], s2[16][33];
    s1[ty][tx] = mmax; s2[ty][tx] = mmin;
    __syncthreads();
#pragma unroll
    for (int h = 8; h; h >>= 1) {
        if (ty < h) {
            s1[ty][tx] = fmaxf(s1[ty][tx], s1[ty + h][tx]);
            s2[ty][tx] = fminf(s2[ty][tx], s2[ty + h][tx]);
        }
        __syncthreads();
    }
    mmax = s1[0][tx]; mmin = s2[0][tx];
    __syncthreads();

    float inv = 4.0f / (1.0f - mmin + EPSV);
    float es = 0.f;
    for (int c = ty; c < C_DIM; c += 16) {
        size_t o = (size_t)c * C_DIM + d;
        float e = __expf((Mo[o] - mmax) * inv);
        Mo[o] = e;
        es += e;
    }
    s1[ty][tx] = es;
    __syncthreads();
#pragma unroll
    for (int h = 8; h; h >>= 1) {
        if (ty < h) s1[ty][tx] += s1[ty + h][tx];
        __syncthreads();
    }
    float rs = 1.0f / s1[0][tx];
    for (int c = ty; c < C_DIM; c += 16) {
        size_t o = (size_t)c * C_DIM + d;
        Mo[o] *= rs;
    }
}

// ---------------- row ops: L1 normalize over d, convert to bf16 --------------
__global__ __launch_bounds__(512) void row_ops() {
    int c = blockIdx.x, b = blockIdx.y;
    const float* Mp = g_m + (size_t)b * C_DIM * C_DIM + (size_t)c * C_DIM;
    float v = Mp[threadIdx.x];
    float s = v;
    __shared__ float sm[16];
#pragma unroll
    for (int o = 16; o; o >>= 1) s += __shfl_xor_sync(0xffffffffu, s, o);
    if ((threadIdx.x & 31) == 0) sm[threadIdx.x >> 5] = s;
    __syncthreads();
    if (threadIdx.x < 16) {
        float t = sm[threadIdx.x];
#pragma unroll
        for (int o = 8; o; o >>= 1) t += __shfl_xor_sync(0xffffu, t, o);
        if (threadIdx.x == 0) sm[0] = t;
    }
    __syncthreads();
    g_mb[(size_t)b * C_DIM * C_DIM + (size_t)c * C_DIM + threadIdx.x] =
        __float2bfloat16(v / (sm[0] + EPSV));
}

// ---------------- launch ------------------------------------------------------
extern "C" void kernel_launch(void* const* d_in, const int* in_sizes, int n_in,
                              void* d_out, int out_size) {
    const float* x  = (const float*)d_in[0];
    const float* wq = (const float*)d_in[1];
    const float* wk = (const float*)d_in[2];
    const float* wv = (const float*)d_in[3];
    const float* gamma = (const float*)d_in[4];
    float* out = (float*)d_out;

    void *p_xbt, *p_wb, *p_qk, *p_qn, *p_kn, *p_vt, *p_mpart, *p_mb;
    cudaGetSymbolAddress(&p_xbt, g_xbt);
    cudaGetSymbolAddress(&p_wb,  g_wb);
    cudaGetSymbolAddress(&p_qk,  g_qk);
    cudaGetSymbolAddress(&p_qn,  g_qn);
    cudaGetSymbolAddress(&p_kn,  g_kn);
    cudaGetSymbolAddress(&p_vt,  g_vt);
    cudaGetSymbolAddress(&p_mpart, g_mpart);
    cudaGetSymbolAddress(&p_mb,  g_mb);

    cudaFuncSetAttribute(gemm_nt<0>, cudaFuncAttributeMaxDynamicSharedMemorySize, 2 * STG_BYTES);
    cudaFuncSetAttribute(gemm_nt<1>, cudaFuncAttributeMaxDynamicSharedMemorySize, 2 * STG_BYTES);
    cudaFuncSetAttribute(gemm_nt<3>, cudaFuncAttributeMaxDynamicSharedMemorySize, 2 * STG_BYTES);

    const long long CN = (long long)C_DIM * N_DIM;   // 2,097,152
    const long long CC = (long long)C_DIM * C_DIM;   // 262,144

    dim3 tb(32, 8);
    // 1) x -> x^T bf16
    transpose_cvt<<<dim3(N_DIM / 32, C_DIM / 32, BATCH), tb>>>(x, (__nv_bfloat16*)p_xbt);
    // 2) weights -> bf16 (stacked Wq|Wk|Wv)
    cvt_w<<<(C_DIM * C_DIM + 255) / 256, 256>>>(wq, wk, wv);
    // 3) [Q;K] = [Wq;Wk] @ x : M=1024, N=4096, K=512
    gemm_nt<0><<<dim3(N_DIM / BN, 1024 / BM, BATCH), 256, 2 * STG_BYTES>>>(
        (const __nv_bfloat16*)p_wb, (const __nv_bfloat16*)p_xbt, p_qk,
        N_DIM, C_DIM, C_DIM, C_DIM,
        0LL, CN, 2 * CN, 1, 0LL, nullptr, nullptr);
    // 4) V^T = x^T @ Wv^T : M=4096, N=512, K=512, bf16 store
    gemm_nt<3><<<dim3(C_DIM / BN, N_DIM / BM, BATCH), 256, 2 * STG_BYTES>>>(
        (const __nv_bfloat16*)p_xbt, (const __nv_bfloat16*)p_wb + 2 * CC, p_vt,
        C_DIM, C_DIM, C_DIM, C_DIM,
        CN, 0LL, CN, 1, 0LL, nullptr, nullptr);
    // 5) L2-normalize Q,K rows -> bf16
    l2norm_cvt<<<dim3(2 * C_DIM, BATCH), 256>>>();
    // 6) M partials = Qn @ Kn^T, split-K=4 : per-chunk K=1024
    gemm_nt<0><<<dim3(C_DIM / BN, C_DIM / BM, BATCH * SKM), 256, 2 * STG_BYTES>>>(
        (const __nv_bfloat16*)p_qn, (const __nv_bfloat16*)p_kn, p_mpart,
        C_DIM, N_DIM / SKM, N_DIM, N_DIM,
        CN, CN, CC, SKM, (long long)BATCH * CC, nullptr, nullptr);
    // 7) column-wise: sum partials + cosine-dist normalize + softmax
    col_ops<<<dim3(C_DIM / 32, BATCH), dim3(32, 16)>>>();
    // 8) row-wise L1 normalize -> bf16
    row_ops<<<dim3(C_DIM, BATCH), 512>>>();
    // 9) out = x + gamma * (M @ V) : M=512, N=4096, K=512
    gemm_nt<1><<<dim3(N_DIM / BN, C_DIM / BM, BATCH), 256, 2 * STG_BYTES>>>(
        (const __nv_bfloat16*)p_mb, (const __nv_bfloat16*)p_vt, out,
        N_DIM, C_DIM, C_DIM, C_DIM,
        CC, CN, CN, 1, 0LL, x, gamma);
}

// round 4
// speedup vs baseline: 1.8019x; 1.0245x over previous
#include <cuda_runtime.h>
#include <cuda_bf16.h>
#include <cstdint>

#define BATCH 8
#define C_DIM 512
#define N_DIM 4096
#define EPSV  1e-6f
#define SKM   2          // split-K for M = Q K^T

// ---------------- scratch (device globals) -----------------------------------
__device__ __nv_bfloat16 g_xbt[(size_t)BATCH * N_DIM * C_DIM];      // x^T bf16 [b][n][c]
__device__ __nv_bfloat16 g_wb[3ULL * C_DIM * C_DIM];                // Wq|Wk|Wv bf16
__device__ __nv_bfloat16 g_qkb[(size_t)BATCH * 2 * C_DIM * N_DIM];  // Q,K bf16 [b][1024][4096]
__device__ float         g_nrm[(size_t)BATCH * 2 * C_DIM];          // row sum-of-squares
__device__ __nv_bfloat16 g_vt[(size_t)BATCH * N_DIM * C_DIM];       // V^T bf16
__device__ float         g_mpart[(size_t)SKM * BATCH * C_DIM * C_DIM];
__device__ float         g_m[(size_t)BATCH * C_DIM * C_DIM];
__device__ __nv_bfloat16 g_mb[(size_t)BATCH * C_DIM * C_DIM];

// ---------------- helpers -----------------------------------------------------
__device__ __forceinline__ uint32_t smem_u32(const void* p) {
    return (uint32_t)__cvta_generic_to_shared(p);
}
__device__ __forceinline__ void cpa16(uint32_t d, const void* s) {
    asm volatile("cp.async.cg.shared.global [%0], [%1], 16;\n" :: "r"(d), "l"(s));
}
__device__ __forceinline__ void ldsm4(uint32_t& r0, uint32_t& r1, uint32_t& r2, uint32_t& r3,
                                      uint32_t a) {
    asm volatile("ldmatrix.sync.aligned.m8n8.x4.shared.b16 {%0,%1,%2,%3}, [%4];\n"
                 : "=r"(r0), "=r"(r1), "=r"(r2), "=r"(r3) : "r"(a));
}
__device__ __forceinline__ void mma16816(float* c, const uint32_t* a, uint32_t b0, uint32_t b1) {
    asm volatile("mma.sync.aligned.m16n8k16.row.col.f32.bf16.bf16.f32 "
                 "{%0,%1,%2,%3}, {%4,%5,%6,%7}, {%8,%9}, {%0,%1,%2,%3};\n"
                 : "+f"(c[0]), "+f"(c[1]), "+f"(c[2]), "+f"(c[3])
                 : "r"(a[0]), "r"(a[1]), "r"(a[2]), "r"(a[3]), "r"(b0), "r"(b1));
}

// ---------------- bf16 NT GEMM, 128x256 CTA, 64x64 warp tile -----------------
// C[M,N] = sum_k A[m][k]*B[n][k].  3-stage cp.async ring, BK=64.
// EPI 0: fp32 store.   EPI 1: C = X + gamma*acc (fp32).
// EPI 3: bf16 store.   EPI 4: bf16 store + per-row sumsq atomicAdd into nrm.
#define BM 128
#define BN 256
#define BK 64
#define NSTG 3
#define STG_A 16384
#define STG_B 32768
#define STG (STG_A + STG_B)
#define SMEM_DYN (NSTG * STG)   // 147456

template <int EPI>
__global__ __launch_bounds__(256, 1) void gemm_nt(
    const __nv_bfloat16* __restrict__ A, const __nv_bfloat16* __restrict__ B,
    void* __restrict__ Cv, int Nld, int K, int lda, int ldb,
    long long strA, long long strB, long long strC, int SK, long long kcStr,
    const float* __restrict__ X, const float* __restrict__ gamma,
    float* __restrict__ nrm)
{
    extern __shared__ __align__(1024) char smraw[];
    int bz = blockIdx.z;
    int b = bz / SK, kc = bz - b * SK;
    A += (size_t)b * strA + (size_t)kc * K;
    B += (size_t)b * strB + (size_t)kc * K;

    int m0 = blockIdx.y * BM, n0 = blockIdx.x * BN;
    int tid = threadIdx.x, lane = tid & 31, w = tid >> 5;
    int wm = (w & 1) * 64;      // 2 warps in m
    int wn = (w >> 1) * 64;     // 4 warps in n
    int r = lane >> 2, q = lane & 3;
    uint32_t sbase = smem_u32(smraw);

    float acc[4][8][4];
#pragma unroll
    for (int mi = 0; mi < 4; mi++)
#pragma unroll
        for (int ni = 0; ni < 8; ni++)
#pragma unroll
            for (int t = 0; t < 4; t++) acc[mi][ni][t] = 0.f;

    int lr = tid >> 3, lc = tid & 7;

    auto load_stage = [&](int kt) {
        int s = kt % NSTG;
        uint32_t sA = sbase + s * STG;
        uint32_t sB = sA + STG_A;
        const __nv_bfloat16* Ag = A + (size_t)kt * BK;
        const __nv_bfloat16* Bg = B + (size_t)kt * BK;
#pragma unroll
        for (int p = 0; p < 4; p++) {
            int row = lr + p * 32;
            cpa16(sA + row * 128 + ((lc ^ (row & 7)) << 4),
                  Ag + (size_t)(m0 + row) * lda + lc * 8);
        }
#pragma unroll
        for (int p = 0; p < 8; p++) {
            int row = lr + p * 32;
            cpa16(sB + row * 128 + ((lc ^ (row & 7)) << 4),
                  Bg + (size_t)(n0 + row) * ldb + lc * 8);
        }
        asm volatile("cp.async.commit_group;\n");
    };

    int nk = K / BK;   // >= 8
    load_stage(0);
    load_stage(1);

    for (int kt = 0; kt < nk; kt++) {
        if (kt < nk - 1) asm volatile("cp.async.wait_group 1;\n" ::: "memory");
        else             asm volatile("cp.async.wait_group 0;\n" ::: "memory");
        __syncthreads();

        int s = kt % NSTG;
        uint32_t sA = sbase + s * STG;
        uint32_t sB = sA + STG_A;
#pragma unroll
        for (int ks = 0; ks < BK / 16; ks++) {
            uint32_t ra[4][4], rb[4][4];
            int kca = ks * 2 + (lane >> 4);
#pragma unroll
            for (int mi = 0; mi < 4; mi++) {
                int row = wm + mi * 16 + (lane & 15);
                ldsm4(ra[mi][0], ra[mi][1], ra[mi][2], ra[mi][3],
                      sA + row * 128 + ((kca ^ (row & 7)) << 4));
            }
            int kcb = ks * 2 + ((lane >> 3) & 1);
            int rbo = (lane & 7) + ((lane >> 4) << 3);
#pragma unroll
            for (int nj = 0; nj < 4; nj++) {
                int row = wn + nj * 16 + rbo;
                ldsm4(rb[nj][0], rb[nj][1], rb[nj][2], rb[nj][3],
                      sB + row * 128 + ((kcb ^ (row & 7)) << 4));
            }
#pragma unroll
            for (int mi = 0; mi < 4; mi++)
#pragma unroll
                for (int nj = 0; nj < 4; nj++) {
                    mma16816(acc[mi][2 * nj],     ra[mi], rb[nj][0], rb[nj][1]);
                    mma16816(acc[mi][2 * nj + 1], ra[mi], rb[nj][2], rb[nj][3]);
                }
        }
        __syncthreads();
        if (kt + 2 < nk) load_stage(kt + 2);
    }

    // ---------------- epilogue ----------------
    if (EPI == 3 || EPI == 4) {
        __nv_bfloat16* C = (__nv_bfloat16*)Cv + (size_t)b * strC;
#pragma unroll
        for (int mi = 0; mi < 4; mi++) {
            float s0 = 0.f, s1 = 0.f;
#pragma unroll
            for (int ni = 0; ni < 8; ni++) {
                int row = m0 + wm + mi * 16 + r;
                int col = n0 + wn + (ni >> 1) * 16 + (ni & 1) * 8 + 2 * q;
                *(__nv_bfloat162*)&C[(size_t)row * Nld + col] =
                    __floats2bfloat162_rn(acc[mi][ni][0], acc[mi][ni][1]);
                *(__nv_bfloat162*)&C[(size_t)(row + 8) * Nld + col] =
                    __floats2bfloat162_rn(acc[mi][ni][2], acc[mi][ni][3]);
                if (EPI == 4) {
                    s0 += acc[mi][ni][0] * acc[mi][ni][0] + acc[mi][ni][1] * acc[mi][ni][1];
                    s1 += acc[mi][ni][2] * acc[mi][ni][2] + acc[mi][ni][3] * acc[mi][ni][3];
                }
            }
            if (EPI == 4) {
                s0 += __shfl_xor_sync(0xffffffffu, s0, 1);
                s0 += __shfl_xor_sync(0xffffffffu, s0, 2);
                s1 += __shfl_xor_sync(0xffffffffu, s1, 1);
                s1 += __shfl_xor_sync(0xffffffffu, s1, 2);
                if (q == 0) {
                    int row = m0 + wm + mi * 16 + r;
                    atomicAdd(&nrm[(size_t)b * 2 * C_DIM + row], s0);
                    atomicAdd(&nrm[(size_t)b * 2 * C_DIM + row + 8], s1);
                }
            }
        }
    } else {
        float* C = (float*)Cv + (size_t)b * strC + (size_t)kc * kcStr;
        float g = 0.f;
        const float* xb = nullptr;
        if (EPI == 1) { g = gamma[0]; xb = X + (size_t)b * strC; }
#pragma unroll
        for (int mi = 0; mi < 4; mi++)
#pragma unroll
            for (int ni = 0; ni < 8; ni++) {
                int row = m0 + wm + mi * 16 + r;
                int col = n0 + wn + (ni >> 1) * 16 + (ni & 1) * 8 + 2 * q;
                size_t o0 = (size_t)row * Nld + col;
                size_t o1 = (size_t)(row + 8) * Nld + col;
                if (EPI == 0) {
                    *(float2*)&C[o0] = make_float2(acc[mi][ni][0], acc[mi][ni][1]);
                    *(float2*)&C[o1] = make_float2(acc[mi][ni][2], acc[mi][ni][3]);
                } else {
                    float2 x0 = *(const float2*)&xb[o0];
                    float2 x1 = *(const float2*)&xb[o1];
                    *(float2*)&C[o0] = make_float2(x0.x + g * acc[mi][ni][0],
                                                   x0.y + g * acc[mi][ni][1]);
                    *(float2*)&C[o1] = make_float2(x1.x + g * acc[mi][ni][2],
                                                   x1.y + g * acc[mi][ni][3]);
                }
            }
    }
}

// ---------------- transpose + fp32->bf16 convert -----------------------------
__global__ void transpose_cvt(const float* __restrict__ src, __nv_bfloat16* __restrict__ dst) {
    __shared__ float tile[32][33];
    int b = blockIdx.z;
    const float* s = src + (size_t)b * C_DIM * N_DIM;
    __nv_bfloat16* d = dst + (size_t)b * C_DIM * N_DIM;
    int n0 = blockIdx.x * 32, c0 = blockIdx.y * 32;
#pragma unroll
    for (int i = 0; i < 32; i += 8)
        tile[threadIdx.y + i][threadIdx.x] =
            s[(size_t)(c0 + threadIdx.y + i) * N_DIM + n0 + threadIdx.x];
    __syncthreads();
#pragma unroll
    for (int i = 0; i < 32; i += 8)
        d[(size_t)(n0 + threadIdx.y + i) * C_DIM + c0 + threadIdx.x] =
            __float2bfloat16(tile[threadIdx.x][threadIdx.y + i]);
}

__global__ void cvt_w(const float* __restrict__ wq, const float* __restrict__ wk,
                      const float* __restrict__ wv) {
    int i = blockIdx.x * blockDim.x + threadIdx.x;
    if (i < C_DIM * C_DIM) {
        g_wb[i]                     = __float2bfloat16(wq[i]);
        g_wb[i + C_DIM * C_DIM]     = __float2bfloat16(wk[i]);
        g_wb[i + 2 * C_DIM * C_DIM] = __float2bfloat16(wv[i]);
    }
    if (i < BATCH * 2 * C_DIM) g_nrm[i] = 0.f;
}

// ---------------- col ops: partial sum, norm-scale, cosine softmax ------------
// block (32 d, 16 c-strides), grid (C_DIM/32, BATCH)
__global__ __launch_bounds__(512) void col_ops() {
    int b = blockIdx.y;
    int tx = threadIdx.x, ty = threadIdx.y;
    int d = blockIdx.x * 32 + tx;
    const size_t cc = (size_t)C_DIM * C_DIM;
    float* Mo = g_m + (size_t)b * cc;
    const float* P = g_mpart + (size_t)b * cc;
    const size_t ks = (size_t)BATCH * cc;
    const float* nb = g_nrm + (size_t)b * 2 * C_DIM;

    __shared__ float inq_s[C_DIM];
    int li = ty * 32 + tx;
    inq_s[li] = rsqrtf(nb[li]);
    float ink = rsqrtf(nb[C_DIM + d]);
    __syncthreads();

    float mmax = -1e30f, mmin = 1e30f;
    for (int c = ty; c < C_DIM; c += 16) {
        size_t o = (size_t)c * C_DIM + d;
        float m = (P[o] + P[o + ks]) * inq_s[c] * ink;
        Mo[o] = m;
        mmax = fmaxf(mmax, m);
        mmin = fminf(mmin, m);
    }
    __shared__ float s1[16][33], s2[16][33];
    s1[ty][tx] = mmax; s2[ty][tx] = mmin;
    __syncthreads();
#pragma unroll
    for (int h = 8; h; h >>= 1) {
        if (ty < h) {
            s1[ty][tx] = fmaxf(s1[ty][tx], s1[ty + h][tx]);
            s2[ty][tx] = fminf(s2[ty][tx], s2[ty + h][tx]);
        }
        __syncthreads();
    }
    mmax = s1[0][tx]; mmin = s2[0][tx];
    __syncthreads();

    float inv = 4.0f / (1.0f - mmin + EPSV);
    float es = 0.f;
    for (int c = ty; c < C_DIM; c += 16) {
        size_t o = (size_t)c * C_DIM + d;
        float e = __expf((Mo[o] - mmax) * inv);
        Mo[o] = e;
        es += e;
    }
    s1[ty][tx] = es;
    __syncthreads();
#pragma unroll
    for (int h = 8; h; h >>= 1) {
        if (ty < h) s1[ty][tx] += s1[ty + h][tx];
        __syncthreads();
    }
    float rs = 1.0f / s1[0][tx];
    for (int c = ty; c < C_DIM; c += 16) {
        size_t o = (size_t)c * C_DIM + d;
        Mo[o] *= rs;
    }
}

// ---------------- row ops: L1 normalize over d, convert to bf16 --------------
__global__ __launch_bounds__(512) void row_ops() {
    int c = blockIdx.x, b = blockIdx.y;
    const float* Mp = g_m + (size_t)b * C_DIM * C_DIM + (size_t)c * C_DIM;
    float v = Mp[threadIdx.x];
    float s = v;
    __shared__ float sm[16];
#pragma unroll
    for (int o = 16; o; o >>= 1) s += __shfl_xor_sync(0xffffffffu, s, o);
    if ((threadIdx.x & 31) == 0) sm[threadIdx.x >> 5] = s;
    __syncthreads();
    if (threadIdx.x < 16) {
        float t = sm[threadIdx.x];
#pragma unroll
        for (int o = 8; o; o >>= 1) t += __shfl_xor_sync(0xffffu, t, o);
        if (threadIdx.x == 0) sm[0] = t;
    }
    __syncthreads();
    g_mb[(size_t)b * C_DIM * C_DIM + (size_t)c * C_DIM + threadIdx.x] =
        __float2bfloat16(v / (sm[0] + EPSV));
}

// ---------------- launch ------------------------------------------------------
extern "C" void kernel_launch(void* const* d_in, const int* in_sizes, int n_in,
                              void* d_out, int out_size) {
    const float* x  = (const float*)d_in[0];
    const float* wq = (const float*)d_in[1];
    const float* wk = (const float*)d_in[2];
    const float* wv = (const float*)d_in[3];
    const float* gamma = (const float*)d_in[4];
    float* out = (float*)d_out;

    void *p_xbt, *p_wb, *p_qkb, *p_nrm, *p_vt, *p_mpart, *p_mb;
    cudaGetSymbolAddress(&p_xbt, g_xbt);
    cudaGetSymbolAddress(&p_wb,  g_wb);
    cudaGetSymbolAddress(&p_qkb, g_qkb);
    cudaGetSymbolAddress(&p_nrm, g_nrm);
    cudaGetSymbolAddress(&p_vt,  g_vt);
    cudaGetSymbolAddress(&p_mpart, g_mpart);
    cudaGetSymbolAddress(&p_mb,  g_mb);

    cudaFuncSetAttribute(gemm_nt<0>, cudaFuncAttributeMaxDynamicSharedMemorySize, SMEM_DYN);
    cudaFuncSetAttribute(gemm_nt<1>, cudaFuncAttributeMaxDynamicSharedMemorySize, SMEM_DYN);
    cudaFuncSetAttribute(gemm_nt<3>, cudaFuncAttributeMaxDynamicSharedMemorySize, SMEM_DYN);
    cudaFuncSetAttribute(gemm_nt<4>, cudaFuncAttributeMaxDynamicSharedMemorySize, SMEM_DYN);

    const long long CN = (long long)C_DIM * N_DIM;
    const long long CC = (long long)C_DIM * C_DIM;

    dim3 tb(32, 8);
    // 1) x -> x^T bf16
    transpose_cvt<<<dim3(N_DIM / 32, C_DIM / 32, BATCH), tb>>>(x, (__nv_bfloat16*)p_xbt);
    // 2) weights -> bf16, zero norms
    cvt_w<<<(C_DIM * C_DIM + 255) / 256, 256>>>(wq, wk, wv);
    // 3) [Q;K] = [Wq;Wk] @ x : M=1024, N=4096, K=512 -> bf16 + row sumsq
    gemm_nt<4><<<dim3(N_DIM / BN, 1024 / BM, BATCH), 256, SMEM_DYN>>>(
        (const __nv_bfloat16*)p_wb, (const __nv_bfloat16*)p_xbt, p_qkb,
        N_DIM, C_DIM, C_DIM, C_DIM,
        0LL, CN, 2 * CN, 1, 0LL, nullptr, nullptr, (float*)p_nrm);
    // 4) V^T = x^T @ Wv^T : M=4096, N=512, K=512 -> bf16
    gemm_nt<3><<<dim3(C_DIM / BN, N_DIM / BM, BATCH), 256, SMEM_DYN>>>(
        (const __nv_bfloat16*)p_xbt, (const __nv_bfloat16*)p_wb + 2 * CC, p_vt,
        C_DIM, C_DIM, C_DIM, C_DIM,
        CN, 0LL, CN, 1, 0LL, nullptr, nullptr, nullptr);
    // 5) G partials = Q @ K^T (unnormalized), split-K=2
    gemm_nt<0><<<dim3(C_DIM / BN, C_DIM / BM, BATCH * SKM), 256, SMEM_DYN>>>(
        (const __nv_bfloat16*)p_qkb,
        (const __nv_bfloat16*)p_qkb + (size_t)C_DIM * N_DIM, p_mpart,
        C_DIM, N_DIM / SKM, N_DIM, N_DIM,
        2 * CN, 2 * CN, CC, SKM, (long long)BATCH * CC, nullptr, nullptr, nullptr);
    // 6) column-wise: sum partials, scale by 1/(|Q||K|), cosine softmax
    col_ops<<<dim3(C_DIM / 32, BATCH), dim3(32, 16)>>>();
    // 7) row-wise L1 normalize -> bf16
    row_ops<<<dim3(C_DIM, BATCH), 512>>>();
    // 8) out = x + gamma * (M @ V) : M=512, N=4096, K=512
    gemm_nt<1><<<dim3(N_DIM / BN, C_DIM / BM, BATCH), 256, SMEM_DYN>>>(
        (const __nv_bfloat16*)p_mb, (const __nv_bfloat16*)p_vt, out,
        N_DIM, C_DIM, C_DIM, C_DIM,
        CC, CN, CN, 1, 0LL, x, gamma, nullptr);
}

// round 5
// speedup vs baseline: 2.2360x; 1.2409x over previous
#include <cuda_runtime.h>
#include <cuda_bf16.h>
#include <cstdint>

#define BATCH 8
#define C_DIM 512
#define N_DIM 4096
#define EPSV  1e-6f
#define SKM   4          // split-K for G = Q K^T

// ---------------- scratch (device globals) -----------------------------------
__device__ __nv_bfloat16 g_xbt[(size_t)BATCH * N_DIM * C_DIM];      // x^T bf16 [b][n][c]
__device__ __nv_bfloat16 g_wb[3ULL * C_DIM * C_DIM];                // Wq|Wk|Wv^T bf16
__device__ __nv_bfloat16 g_qkb[(size_t)BATCH * 2 * C_DIM * N_DIM];  // Q,K bf16
__device__ float         g_nrm[(size_t)BATCH * 2 * C_DIM];          // row sum-of-squares
__device__ float         g_mpart[(size_t)SKM * BATCH * C_DIM * C_DIM];
__device__ float         g_m[(size_t)BATCH * C_DIM * C_DIM];
__device__ __nv_bfloat16 g_mb[(size_t)BATCH * C_DIM * C_DIM];       // M bf16
__device__ __nv_bfloat16 g_mw[(size_t)BATCH * C_DIM * C_DIM];       // M @ Wv bf16

// ---------------- helpers -----------------------------------------------------
__device__ __forceinline__ uint32_t smem_u32(const void* p) {
    return (uint32_t)__cvta_generic_to_shared(p);
}
__device__ __forceinline__ void cpa16(uint32_t d, const void* s) {
    asm volatile("cp.async.cg.shared.global [%0], [%1], 16;\n" :: "r"(d), "l"(s));
}
__device__ __forceinline__ void ldsm4(uint32_t& r0, uint32_t& r1, uint32_t& r2, uint32_t& r3,
                                      uint32_t a) {
    asm volatile("ldmatrix.sync.aligned.m8n8.x4.shared.b16 {%0,%1,%2,%3}, [%4];\n"
                 : "=r"(r0), "=r"(r1), "=r"(r2), "=r"(r3) : "r"(a));
}
__device__ __forceinline__ void mma16816(float* c, const uint32_t* a, uint32_t b0, uint32_t b1) {
    asm volatile("mma.sync.aligned.m16n8k16.row.col.f32.bf16.bf16.f32 "
                 "{%0,%1,%2,%3}, {%4,%5,%6,%7}, {%8,%9}, {%0,%1,%2,%3};\n"
                 : "+f"(c[0]), "+f"(c[1]), "+f"(c[2]), "+f"(c[3])
                 : "r"(a[0]), "r"(a[1]), "r"(a[2]), "r"(a[3]), "r"(b0), "r"(b1));
}

// ---------------- bf16 NT GEMM: 128x128 CTA, 64x32 warp tile, 2-stage ---------
// C[M,N] = sum_k A[m][k]*B[n][k].
// EPI 0: fp32 store.  EPI 1: C = X + gamma*acc (fp32).
// EPI 3: bf16 store.  EPI 4: bf16 store + per-row sumsq atomicAdd into nrm.
#define BM 128
#define BN 128
#define BK 64
#define STG_BYTES 32768   // (128+128)*64*2 per stage

template <int EPI>
__global__ __launch_bounds__(256, 2) void gemm_nt(
    const __nv_bfloat16* __restrict__ A, const __nv_bfloat16* __restrict__ B,
    void* __restrict__ Cv, int Nld, int K, int lda, int ldb,
    long long strA, long long strB, long long strC, int SK, long long kcStr,
    const float* __restrict__ X, const float* __restrict__ gamma,
    float* __restrict__ nrm)
{
    extern __shared__ char smraw[];
    int bz = blockIdx.z;
    int b = bz / SK, kc = bz - b * SK;
    A += (size_t)b * strA + (size_t)kc * K;
    B += (size_t)b * strB + (size_t)kc * K;

    int m0 = blockIdx.y * BM, n0 = blockIdx.x * BN;
    int tid = threadIdx.x;
    int lane = tid & 31, w = tid >> 5;
    int wm = (w & 1) * 64;
    int wn = (w >> 1) * 32;
    int r = lane >> 2, q = lane & 3;

    uint32_t sbase = smem_u32(smraw);

    float acc[4][4][4];
#pragma unroll
    for (int mi = 0; mi < 4; mi++)
#pragma unroll
        for (int ni = 0; ni < 4; ni++)
#pragma unroll
            for (int t = 0; t < 4; t++) acc[mi][ni][t] = 0.f;

    int lr = tid >> 3;     // 0..31
    int lc = tid & 7;      // 16B chunk index

    auto issue = [&](int kt, int s) {
        uint32_t sA = sbase + s * STG_BYTES;
        uint32_t sB = sA + 16384;
        const __nv_bfloat16* Ag = A + (size_t)kt * BK;
        const __nv_bfloat16* Bg = B + (size_t)kt * BK;
#pragma unroll
        for (int p = 0; p < 4; p++) {
            int row = lr + p * 32;
            uint32_t off = row * 128 + ((lc ^ (row & 7)) << 4);
            cpa16(sA + off, Ag + (size_t)(m0 + row) * lda + lc * 8);
            cpa16(sB + off, Bg + (size_t)(n0 + row) * ldb + lc * 8);
        }
    };

    int nk = K / BK;
    issue(0, 0);
    asm volatile("cp.async.commit_group;\n");

    for (int kt = 0; kt < nk; kt++) {
        int cur = kt & 1;
        if (kt + 1 < nk) {
            issue(kt + 1, cur ^ 1);
            asm volatile("cp.async.commit_group;\n");
            asm volatile("cp.async.wait_group 1;\n");
        } else {
            asm volatile("cp.async.wait_group 0;\n");
        }
        __syncthreads();

        uint32_t sA = sbase + cur * STG_BYTES;
        uint32_t sB = sA + 16384;
#pragma unroll
        for (int ks = 0; ks < BK / 16; ks++) {
            uint32_t ra[4][4], rb[2][4];
            int kca = ks * 2 + (lane >> 4);
#pragma unroll
            for (int mi = 0; mi < 4; mi++) {
                int row = wm + mi * 16 + (lane & 15);
                ldsm4(ra[mi][0], ra[mi][1], ra[mi][2], ra[mi][3],
                      sA + row * 128 + ((kca ^ (row & 7)) << 4));
            }
            int kcb = ks * 2 + ((lane >> 3) & 1);
            int rbo = (lane & 7) + ((lane >> 4) << 3);
#pragma unroll
            for (int nj = 0; nj < 2; nj++) {
                int row = wn + nj * 16 + rbo;
                ldsm4(rb[nj][0], rb[nj][1], rb[nj][2], rb[nj][3],
                      sB + row * 128 + ((kcb ^ (row & 7)) << 4));
            }
#pragma unroll
            for (int mi = 0; mi < 4; mi++)
#pragma unroll
                for (int nj = 0; nj < 2; nj++) {
                    mma16816(acc[mi][2 * nj],     ra[mi], rb[nj][0], rb[nj][1]);
                    mma16816(acc[mi][2 * nj + 1], ra[mi], rb[nj][2], rb[nj][3]);
                }
        }
        __syncthreads();
    }

    // ---------------- epilogue ----------------
    if (EPI == 3 || EPI == 4) {
        __nv_bfloat16* C = (__nv_bfloat16*)Cv + (size_t)b * strC;
#pragma unroll
        for (int mi = 0; mi < 4; mi++) {
            float s0 = 0.f, s1 = 0.f;
#pragma unroll
            for (int ni = 0; ni < 4; ni++) {
                int row = m0 + wm + mi * 16 + r;
                int col = n0 + wn + ni * 8 + 2 * q;
                *(__nv_bfloat162*)&C[(size_t)row * Nld + col] =
                    __floats2bfloat162_rn(acc[mi][ni][0], acc[mi][ni][1]);
                *(__nv_bfloat162*)&C[(size_t)(row + 8) * Nld + col] =
                    __floats2bfloat162_rn(acc[mi][ni][2], acc[mi][ni][3]);
                if (EPI == 4) {
                    s0 += acc[mi][ni][0] * acc[mi][ni][0] + acc[mi][ni][1] * acc[mi][ni][1];
                    s1 += acc[mi][ni][2] * acc[mi][ni][2] + acc[mi][ni][3] * acc[mi][ni][3];
                }
            }
            if (EPI == 4) {
                s0 += __shfl_xor_sync(0xffffffffu, s0, 1);
                s0 += __shfl_xor_sync(0xffffffffu, s0, 2);
                s1 += __shfl_xor_sync(0xffffffffu, s1, 1);
                s1 += __shfl_xor_sync(0xffffffffu, s1, 2);
                if (q == 0) {
                    int row = m0 + wm + mi * 16 + r;
                    atomicAdd(&nrm[(size_t)b * 2 * C_DIM + row], s0);
                    atomicAdd(&nrm[(size_t)b * 2 * C_DIM + row + 8], s1);
                }
            }
        }
    } else {
        float* C = (float*)Cv + (size_t)b * strC + (size_t)kc * kcStr;
        float g = 0.f;
        const float* xb = nullptr;
        if (EPI == 1) { g = gamma[0]; xb = X + (size_t)b * strC; }
#pragma unroll
        for (int mi = 0; mi < 4; mi++)
#pragma unroll
            for (int ni = 0; ni < 4; ni++) {
                int row = m0 + wm + mi * 16 + r;
                int col = n0 + wn + ni * 8 + 2 * q;
                size_t o0 = (size_t)row * Nld + col;
                size_t o1 = (size_t)(row + 8) * Nld + col;
                if (EPI == 0) {
                    *(float2*)&C[o0] = make_float2(acc[mi][ni][0], acc[mi][ni][1]);
                    *(float2*)&C[o1] = make_float2(acc[mi][ni][2], acc[mi][ni][3]);
                } else {
                    float2 x0 = *(const float2*)&xb[o0];
                    float2 x1 = *(const float2*)&xb[o1];
                    *(float2*)&C[o0] = make_float2(x0.x + g * acc[mi][ni][0],
                                                   x0.y + g * acc[mi][ni][1]);
                    *(float2*)&C[o1] = make_float2(x1.x + g * acc[mi][ni][2],
                                                   x1.y + g * acc[mi][ni][3]);
                }
            }
    }
}

// ---------------- transpose + fp32->bf16 convert -----------------------------
__global__ void transpose_cvt(const float* __restrict__ src, __nv_bfloat16* __restrict__ dst) {
    __shared__ float tile[32][33];
    int b = blockIdx.z;
    const float* s = src + (size_t)b * C_DIM * N_DIM;
    __nv_bfloat16* d = dst + (size_t)b * C_DIM * N_DIM;
    int n0 = blockIdx.x * 32, c0 = blockIdx.y * 32;
#pragma unroll
    for (int i = 0; i < 32; i += 8)
        tile[threadIdx.y + i][threadIdx.x] =
            s[(size_t)(c0 + threadIdx.y + i) * N_DIM + n0 + threadIdx.x];
    __syncthreads();
#pragma unroll
    for (int i = 0; i < 32; i += 8)
        d[(size_t)(n0 + threadIdx.y + i) * C_DIM + c0 + threadIdx.x] =
            __float2bfloat16(tile[threadIdx.x][threadIdx.y + i]);
}

// weights -> bf16: Wq, Wk as-is; Wv transposed (for MW = M @ Wv as NT GEMM)
__global__ void cvt_w(const float* __restrict__ wq, const float* __restrict__ wk,
                      const float* __restrict__ wv) {
    int i = blockIdx.x * blockDim.x + threadIdx.x;
    if (i < C_DIM * C_DIM) {
        g_wb[i]                 = __float2bfloat16(wq[i]);
        g_wb[i + C_DIM * C_DIM] = __float2bfloat16(wk[i]);
        int o = i >> 9, c = i & (C_DIM - 1);
        g_wb[2 * C_DIM * C_DIM + c * C_DIM + o] = __float2bfloat16(wv[i]);  // Wv^T
    }
    if (i < BATCH * 2 * C_DIM) g_nrm[i] = 0.f;
}

// ---------------- col ops: sum partials, norm-scale, cosine softmax -----------
__global__ __launch_bounds__(512) void col_ops() {
    int b = blockIdx.y;
    int tx = threadIdx.x, ty = threadIdx.y;
    int d = blockIdx.x * 32 + tx;
    const size_t cc = (size_t)C_DIM * C_DIM;
    float* Mo = g_m + (size_t)b * cc;
    const float* P = g_mpart + (size_t)b * cc;
    const size_t ks = (size_t)BATCH * cc;
    const float* nb = g_nrm + (size_t)b * 2 * C_DIM;

    __shared__ float inq_s[C_DIM];
    int li = ty * 32 + tx;
    inq_s[li] = rsqrtf(nb[li]);
    float ink = rsqrtf(nb[C_DIM + d]);
    __syncthreads();

    float mmax = -1e30f, mmin = 1e30f;
    for (int c = ty; c < C_DIM; c += 16) {
        size_t o = (size_t)c * C_DIM + d;
        float m = (P[o] + P[o + ks] + P[o + 2 * ks] + P[o + 3 * ks]) * inq_s[c] * ink;
        Mo[o] = m;
        mmax = fmaxf(mmax, m);
        mmin = fminf(mmin, m);
    }
    __shared__ float s1[16][33], s2[16][33];
    s1[ty][tx] = mmax; s2[ty][tx] = mmin;
    __syncthreads();
#pragma unroll
    for (int h = 8; h; h >>= 1) {
        if (ty < h) {
            s1[ty][tx] = fmaxf(s1[ty][tx], s1[ty + h][tx]);
            s2[ty][tx] = fminf(s2[ty][tx], s2[ty + h][tx]);
        }
        __syncthreads();
    }
    mmax = s1[0][tx]; mmin = s2[0][tx];
    __syncthreads();

    float inv = 4.0f / (1.0f - mmin + EPSV);
    float es = 0.f;
    for (int c = ty; c < C_DIM; c += 16) {
        size_t o = (size_t)c * C_DIM + d;
        float e = __expf((Mo[o] - mmax) * inv);
        Mo[o] = e;
        es += e;
    }
    s1[ty][tx] = es;
    __syncthreads();
#pragma unroll
    for (int h = 8; h; h >>= 1) {
        if (ty < h) s1[ty][tx] += s1[ty + h][tx];
        __syncthreads();
    }
    float rs = 1.0f / s1[0][tx];
    for (int c = ty; c < C_DIM; c += 16) {
        size_t o = (size_t)c * C_DIM + d;
        Mo[o] *= rs;
    }
}

// ---------------- row ops: L1 normalize over d -> bf16 ------------------------
__global__ __launch_bounds__(512) void row_ops() {
    int c = blockIdx.x, b = blockIdx.y;
    const float* Mp = g_m + (size_t)b * C_DIM * C_DIM + (size_t)c * C_DIM;
    float v = Mp[threadIdx.x];
    float s = v;
    __shared__ float sm[16];
#pragma unroll
    for (int o = 16; o; o >>= 1) s += __shfl_xor_sync(0xffffffffu, s, o);
    if ((threadIdx.x & 31) == 0) sm[threadIdx.x >> 5] = s;
    __syncthreads();
    if (threadIdx.x < 16) {
        float t = sm[threadIdx.x];
#pragma unroll
        for (int o = 8; o; o >>= 1) t += __shfl_xor_sync(0xffffu, t, o);
        if (threadIdx.x == 0) sm[0] = t;
    }
    __syncthreads();
    g_mb[(size_t)b * C_DIM * C_DIM + (size_t)c * C_DIM + threadIdx.x] =
        __float2bfloat16(v / (sm[0] + EPSV));
}

// ---------------- launch ------------------------------------------------------
extern "C" void kernel_launch(void* const* d_in, const int* in_sizes, int n_in,
                              void* d_out, int out_size) {
    const float* x  = (const float*)d_in[0];
    const float* wq = (const float*)d_in[1];
    const float* wk = (const float*)d_in[2];
    const float* wv = (const float*)d_in[3];
    const float* gamma = (const float*)d_in[4];
    float* out = (float*)d_out;

    void *p_xbt, *p_wb, *p_qkb, *p_nrm, *p_mpart, *p_mb, *p_mw;
    cudaGetSymbolAddress(&p_xbt, g_xbt);
    cudaGetSymbolAddress(&p_wb,  g_wb);
    cudaGetSymbolAddress(&p_qkb, g_qkb);
    cudaGetSymbolAddress(&p_nrm, g_nrm);
    cudaGetSymbolAddress(&p_mpart, g_mpart);
    cudaGetSymbolAddress(&p_mb,  g_mb);
    cudaGetSymbolAddress(&p_mw,  g_mw);

    cudaFuncSetAttribute(gemm_nt<0>, cudaFuncAttributeMaxDynamicSharedMemorySize, 2 * STG_BYTES);
    cudaFuncSetAttribute(gemm_nt<1>, cudaFuncAttributeMaxDynamicSharedMemorySize, 2 * STG_BYTES);
    cudaFuncSetAttribute(gemm_nt<3>, cudaFuncAttributeMaxDynamicSharedMemorySize, 2 * STG_BYTES);
    cudaFuncSetAttribute(gemm_nt<4>, cudaFuncAttributeMaxDynamicSharedMemorySize, 2 * STG_BYTES);

    const long long CN = (long long)C_DIM * N_DIM;
    const long long CC = (long long)C_DIM * C_DIM;

    dim3 tb(32, 8);
    // 1) x -> x^T bf16
    transpose_cvt<<<dim3(N_DIM / 32, C_DIM / 32, BATCH), tb>>>(x, (__nv_bfloat16*)p_xbt);
    // 2) weights -> bf16 (Wq | Wk | Wv^T), zero norms
    cvt_w<<<(C_DIM * C_DIM + 255) / 256, 256>>>(wq, wk, wv);
    // 3) [Q;K] = [Wq;Wk] @ x : M=1024, N=4096, K=512 -> bf16 + row sumsq
    gemm_nt<4><<<dim3(N_DIM / BN, 1024 / BM, BATCH), 256, 2 * STG_BYTES>>>(
        (const __nv_bfloat16*)p_wb, (const __nv_bfloat16*)p_xbt, p_qkb,
        N_DIM, C_DIM, C_DIM, C_DIM,
        0LL, CN, 2 * CN, 1, 0LL, nullptr, nullptr, (float*)p_nrm);
    // 4) G partials = Q @ K^T (unnormalized), split-K=4
    gemm_nt<0><<<dim3(C_DIM / BN, C_DIM / BM, BATCH * SKM), 256, 2 * STG_BYTES>>>(
        (const __nv_bfloat16*)p_qkb,
        (const __nv_bfloat16*)p_qkb + (size_t)C_DIM * N_DIM, p_mpart,
        C_DIM, N_DIM / SKM, N_DIM, N_DIM,
        2 * CN, 2 * CN, CC, SKM, (long long)BATCH * CC, nullptr, nullptr, nullptr);
    // 5) column-wise: sum partials, scale by 1/(|Q||K|), cosine softmax
    col_ops<<<dim3(C_DIM / 32, BATCH), dim3(32, 16)>>>();
    // 6) row-wise L1 normalize -> bf16
    row_ops<<<dim3(C_DIM, BATCH), 512>>>();
    // 7) MW = M @ Wv : M=512, N=512, K=512 -> bf16  (B = Wv^T, NT form)
    gemm_nt<3><<<dim3(C_DIM / BN, C_DIM / BM, BATCH), 256, 2 * STG_BYTES>>>(
        (const __nv_bfloat16*)p_mb, (const __nv_bfloat16*)p_wb + 2 * CC, p_mw,
        C_DIM, C_DIM, C_DIM, C_DIM,
        CC, 0LL, CC, 1, 0LL, nullptr, nullptr, nullptr);
    // 8) out = x + gamma * (MW @ x) : M=512, N=4096, K=512  (B = x^T)
    gemm_nt<1><<<dim3(N_DIM / BN, C_DIM / BM, BATCH), 256, 2 * STG_BYTES>>>(
        (const __nv_bfloat16*)p_mw, (const __nv_bfloat16*)p_xbt, out,
        N_DIM, C_DIM, C_DIM, C_DIM,
        CC, CN, CN, 1, 0LL, x, gamma, nullptr);
}

// round 7
// speedup vs baseline: 3.0282x; 1.3543x over previous
#include <cuda_runtime.h>
#include <cuda_bf16.h>
#include <cstdint>

#define BATCH 8
#define C_DIM 512
#define N_DIM 4096
#define EPSV  1e-6f
#define SKM   4          // split-K for S = x x^T

// ---------------- scratch (device globals) -----------------------------------
__device__ __nv_bfloat16 g_xb [(size_t)BATCH * C_DIM * N_DIM];      // x bf16 [b][c][n]
__device__ __nv_bfloat16 g_xbt[(size_t)BATCH * N_DIM * C_DIM];      // x^T bf16 [b][n][c]
__device__ __nv_bfloat16 g_wb[3ULL * C_DIM * C_DIM];                // Wq|Wk|Wv^T bf16
__device__ float         g_spart[(size_t)SKM * BATCH * C_DIM * C_DIM]; // S partials
__device__ __nv_bfloat16 g_sb[(size_t)BATCH * C_DIM * C_DIM];       // S bf16
__device__ __nv_bfloat16 g_ab[(size_t)BATCH * 2 * C_DIM * C_DIM];   // [Aq;Ak] bf16
__device__ float         g_nrm[(size_t)BATCH * 2 * C_DIM];          // |Q_i|^2, |K_i|^2
__device__ float         g_m[(size_t)BATCH * C_DIM * C_DIM];        // G / M fp32
__device__ __nv_bfloat16 g_mb[(size_t)BATCH * C_DIM * C_DIM];       // M bf16
__device__ __nv_bfloat16 g_mw[(size_t)BATCH * C_DIM * C_DIM];       // M @ Wv bf16

// ---------------- helpers -----------------------------------------------------
__device__ __forceinline__ uint32_t smem_u32(const void* p) {
    return (uint32_t)__cvta_generic_to_shared(p);
}
__device__ __forceinline__ void cpa16(uint32_t d, const void* s) {
    asm volatile("cp.async.cg.shared.global [%0], [%1], 16;\n" :: "r"(d), "l"(s));
}
__device__ __forceinline__ void ldsm4(uint32_t& r0, uint32_t& r1, uint32_t& r2, uint32_t& r3,
                                      uint32_t a) {
    asm volatile("ldmatrix.sync.aligned.m8n8.x4.shared.b16 {%0,%1,%2,%3}, [%4];\n"
                 : "=r"(r0), "=r"(r1), "=r"(r2), "=r"(r3) : "r"(a));
}
__device__ __forceinline__ void mma16816(float* c, const uint32_t* a, uint32_t b0, uint32_t b1) {
    asm volatile("mma.sync.aligned.m16n8k16.row.col.f32.bf16.bf16.f32 "
                 "{%0,%1,%2,%3}, {%4,%5,%6,%7}, {%8,%9}, {%0,%1,%2,%3};\n"
                 : "+f"(c[0]), "+f"(c[1]), "+f"(c[2]), "+f"(c[3])
                 : "r"(a[0]), "r"(a[1]), "r"(a[2]), "r"(a[3]), "r"(b0), "r"(b1));
}

// ---------------- bf16 NT GEMM: 128x128 CTA, 64x32 warp tile, 2-stage ---------
// EPI 0: fp32 store.  EPI 1: C = X + gamma*acc (fp32).  EPI 3: bf16 store.
#define BM 128
#define BN 128
#define BK 64
#define STG_BYTES 32768

template <int EPI>
__global__ __launch_bounds__(256, 2) void gemm_nt(
    const __nv_bfloat16* __restrict__ A, const __nv_bfloat16* __restrict__ B,
    void* __restrict__ Cv, int Nld, int K, int lda, int ldb,
    long long strA, long long strB, long long strC, int SK, long long kcStr,
    const float* __restrict__ X, const float* __restrict__ gamma)
{
    extern __shared__ char smraw[];
    int bz = blockIdx.z;
    int b = bz / SK, kc = bz - b * SK;
    A += (size_t)b * strA + (size_t)kc * K;
    B += (size_t)b * strB + (size_t)kc * K;

    int m0 = blockIdx.y * BM, n0 = blockIdx.x * BN;
    int tid = threadIdx.x;
    int lane = tid & 31, w = tid >> 5;
    int wm = (w & 1) * 64;
    int wn = (w >> 1) * 32;
    int r = lane >> 2, q = lane & 3;

    uint32_t sbase = smem_u32(smraw);

    float acc[4][4][4];
#pragma unroll
    for (int mi = 0; mi < 4; mi++)
#pragma unroll
        for (int ni = 0; ni < 4; ni++)
#pragma unroll
            for (int t = 0; t < 4; t++) acc[mi][ni][t] = 0.f;

    int lr = tid >> 3, lc = tid & 7;

    auto issue = [&](int kt, int s) {
        uint32_t sA = sbase + s * STG_BYTES;
        uint32_t sB = sA + 16384;
        const __nv_bfloat16* Ag = A + (size_t)kt * BK;
        const __nv_bfloat16* Bg = B + (size_t)kt * BK;
#pragma unroll
        for (int p = 0; p < 4; p++) {
            int row = lr + p * 32;
            uint32_t off = row * 128 + ((lc ^ (row & 7)) << 4);
            cpa16(sA + off, Ag + (size_t)(m0 + row) * lda + lc * 8);
            cpa16(sB + off, Bg + (size_t)(n0 + row) * ldb + lc * 8);
        }
    };

    int nk = K / BK;
    issue(0, 0);
    asm volatile("cp.async.commit_group;\n");

    for (int kt = 0; kt < nk; kt++) {
        int cur = kt & 1;
        if (kt + 1 < nk) {
            issue(kt + 1, cur ^ 1);
            asm volatile("cp.async.commit_group;\n");
            asm volatile("cp.async.wait_group 1;\n");
        } else {
            asm volatile("cp.async.wait_group 0;\n");
        }
        __syncthreads();

        uint32_t sA = sbase + cur * STG_BYTES;
        uint32_t sB = sA + 16384;
#pragma unroll
        for (int ks = 0; ks < BK / 16; ks++) {
            uint32_t ra[4][4], rb[2][4];
            int kca = ks * 2 + (lane >> 4);
#pragma unroll
            for (int mi = 0; mi < 4; mi++) {
                int row = wm + mi * 16 + (lane & 15);
                ldsm4(ra[mi][0], ra[mi][1], ra[mi][2], ra[mi][3],
                      sA + row * 128 + ((kca ^ (row & 7)) << 4));
            }
            int kcb = ks * 2 + ((lane >> 3) & 1);
            int rbo = (lane & 7) + ((lane >> 4) << 3);
#pragma unroll
            for (int nj = 0; nj < 2; nj++) {
                int row = wn + nj * 16 + rbo;
                ldsm4(rb[nj][0], rb[nj][1], rb[nj][2], rb[nj][3],
                      sB + row * 128 + ((kcb ^ (row & 7)) << 4));
            }
#pragma unroll
            for (int mi = 0; mi < 4; mi++)
#pragma unroll
                for (int nj = 0; nj < 2; nj++) {
                    mma16816(acc[mi][2 * nj],     ra[mi], rb[nj][0], rb[nj][1]);
                    mma16816(acc[mi][2 * nj + 1], ra[mi], rb[nj][2], rb[nj][3]);
                }
        }
        __syncthreads();
    }

    if (EPI == 3) {
        __nv_bfloat16* C = (__nv_bfloat16*)Cv + (size_t)b * strC;
#pragma unroll
        for (int mi = 0; mi < 4; mi++)
#pragma unroll
            for (int ni = 0; ni < 4; ni++) {
                int row = m0 + wm + mi * 16 + r;
                int col = n0 + wn + ni * 8 + 2 * q;
                *(__nv_bfloat162*)&C[(size_t)row * Nld + col] =
                    __floats2bfloat162_rn(acc[mi][ni][0], acc[mi][ni][1]);
                *(__nv_bfloat162*)&C[(size_t)(row + 8) * Nld + col] =
                    __floats2bfloat162_rn(acc[mi][ni][2], acc[mi][ni][3]);
            }
    } else {
        float* C = (float*)Cv + (size_t)b * strC + (size_t)kc * kcStr;
        float g = 0.f;
        const float* xb = nullptr;
        if (EPI == 1) { g = gamma[0]; xb = X + (size_t)b * strC; }
#pragma unroll
        for (int mi = 0; mi < 4; mi++)
#pragma unroll
            for (int ni = 0; ni < 4; ni++) {
                int row = m0 + wm + mi * 16 + r;
                int col = n0 + wn + ni * 8 + 2 * q;
                size_t o0 = (size_t)row * Nld + col;
                size_t o1 = (size_t)(row + 8) * Nld + col;
                if (EPI == 0) {
                    *(float2*)&C[o0] = make_float2(acc[mi][ni][0], acc[mi][ni][1]);
                    *(float2*)&C[o1] = make_float2(acc[mi][ni][2], acc[mi][ni][3]);
                } else {
                    float2 x0 = *(const float2*)&xb[o0];
                    float2 x1 = *(const float2*)&xb[o1];
                    *(float2*)&C[o0] = make_float2(x0.x + g * acc[mi][ni][0],
                                                   x0.y + g * acc[mi][ni][1]);
                    *(float2*)&C[o1] = make_float2(x1.x + g * acc[mi][ni][2],
                                                   x1.y + g * acc[mi][ni][3]);
                }
            }
    }
}

// ---------------- x -> bf16 (straight) + bf16 transposed ----------------------
__global__ void cvt_x(const float* __restrict__ src) {
    __shared__ float tile[32][33];
    int b = blockIdx.z;
    const float* s = src + (size_t)b * C_DIM * N_DIM;
    __nv_bfloat16* ds = g_xb  + (size_t)b * C_DIM * N_DIM;
    __nv_bfloat16* dt = g_xbt + (size_t)b * C_DIM * N_DIM;
    int n0 = blockIdx.x * 32, c0 = blockIdx.y * 32;
#pragma unroll
    for (int i = 0; i < 32; i += 8) {
        float v = s[(size_t)(c0 + threadIdx.y + i) * N_DIM + n0 + threadIdx.x];
        tile[threadIdx.y + i][threadIdx.x] = v;
        ds[(size_t)(c0 + threadIdx.y + i) * N_DIM + n0 + threadIdx.x] = __float2bfloat16(v);
    }
    __syncthreads();
#pragma unroll
    for (int i = 0; i < 32; i += 8)
        dt[(size_t)(n0 + threadIdx.y + i) * C_DIM + c0 + threadIdx.x] =
            __float2bfloat16(tile[threadIdx.x][threadIdx.y + i]);
}

// weights -> bf16: [Wq;Wk] stacked, Wv transposed
__global__ void cvt_w(const float* __restrict__ wq, const float* __restrict__ wk,
                      const float* __restrict__ wv) {
    int i = blockIdx.x * blockDim.x + threadIdx.x;
    if (i < C_DIM * C_DIM) {
        g_wb[i]                 = __float2bfloat16(wq[i]);
        g_wb[i + C_DIM * C_DIM] = __float2bfloat16(wk[i]);
        int o = i >> 9, c = i & (C_DIM - 1);
        g_wb[2 * C_DIM * C_DIM + c * C_DIM + o] = __float2bfloat16(wv[i]);  // Wv^T
    }
}

// ---------------- sum S partials -> bf16 --------------------------------------
__global__ __launch_bounds__(256) void sum_s() {
    size_t i = (size_t)blockIdx.x * 256 + threadIdx.x;
    const size_t tot = (size_t)BATCH * C_DIM * C_DIM;
    if (i < tot) {
        float v = g_spart[i] + g_spart[i + tot] + g_spart[i + 2 * tot] + g_spart[i + 3 * tot];
        g_sb[i] = __float2bfloat16(v);
    }
}

// ---------------- row norms: nrm[b][r] = A[b][r] . W[r] -----------------------
// grid (2*C_DIM/8, BATCH), block 256 (8 warps, one row per warp)
__global__ __launch_bounds__(256) void norm_dots() {
    int b = blockIdx.y;
    int row = blockIdx.x * 8 + (threadIdx.x >> 5);   // 0..1023
    int lane = threadIdx.x & 31;
    const __nv_bfloat162* a =
        (const __nv_bfloat162*)(g_ab + ((size_t)b * 2 * C_DIM + row) * C_DIM);
    const __nv_bfloat162* wr = (const __nv_bfloat162*)(g_wb + (size_t)row * C_DIM);
    float s = 0.f;
#pragma unroll
    for (int i = lane; i < C_DIM / 2; i += 32) {
        __nv_bfloat162 av = a[i], wv2 = wr[i];
        s += __bfloat162float(av.x) * __bfloat162float(wv2.x)
           + __bfloat162float(av.y) * __bfloat162float(wv2.y);
    }
#pragma unroll
    for (int o = 16; o; o >>= 1) s += __shfl_xor_sync(0xffffffffu, s, o);
    if (lane == 0) g_nrm[(size_t)b * 2 * C_DIM + row] = s;
}

// ---------------- col ops: norm-scale + cosine softmax (in place on g_m) ------
__global__ __launch_bounds__(512) void col_ops() {
    int b = blockIdx.y;
    int tx = threadIdx.x, ty = threadIdx.y;
    int d = blockIdx.x * 32 + tx;
    const size_t cc = (size_t)C_DIM * C_DIM;
    float* Mo = g_m + (size_t)b * cc;
    const float* nb = g_nrm + (size_t)b * 2 * C_DIM;

    __shared__ float inq_s[C_DIM];
    int li = ty * 32 + tx;
    inq_s[li] = rsqrtf(nb[li]);
    float ink = rsqrtf(nb[C_DIM + d]);
    __syncthreads();

    float mmax = -1e30f, mmin = 1e30f;
    for (int c = ty; c < C_DIM; c += 16) {
        size_t o = (size_t)c * C_DIM + d;
        float m = Mo[o] * inq_s[c] * ink;
        Mo[o] = m;
        mmax = fmaxf(mmax, m);
        mmin = fminf(mmin, m);
    }
    __shared__ float s1[16][33], s2[16][33];
    s1[ty][tx] = mmax; s2[ty][tx] = mmin;
    __syncthreads();
#pragma unroll
    for (int h = 8; h; h >>= 1) {
        if (ty < h) {
            s1[ty][tx] = fmaxf(s1[ty][tx], s1[ty + h][tx]);
            s2[ty][tx] = fminf(s2[ty][tx], s2[ty + h][tx]);
        }
        __syncthreads();
    }
    mmax = s1[0][tx]; mmin = s2[0][tx];
    __syncthreads();

    float inv = 4.0f / (1.0f - mmin + EPSV);
    float es = 0.f;
    for (int c = ty; c < C_DIM; c += 16) {
        size_t o = (size_t)c * C_DIM + d;
        float e = __expf((Mo[o] - mmax) * inv);
        Mo[o] = e;
        es += e;
    }
    s1[ty][tx] = es;
    __syncthreads();
#pragma unroll
    for (int h = 8; h; h >>= 1) {
        if (ty < h) s1[ty][tx] += s1[ty + h][tx];
        __syncthreads();
    }
    float rs = 1.0f / s1[0][tx];
    for (int c = ty; c < C_DIM; c += 16) {
        size_t o = (size_t)c * C_DIM + d;
        Mo[o] *= rs;
    }
}

// ---------------- row ops: L1 normalize over d -> bf16 ------------------------
__global__ __launch_bounds__(512) void row_ops() {
    int c = blockIdx.x, b = blockIdx.y;
    const float* Mp = g_m + (size_t)b * C_DIM * C_DIM + (size_t)c * C_DIM;
    float v = Mp[threadIdx.x];
    float s = v;
    __shared__ float sm[16];
#pragma unroll
    for (int o = 16; o; o >>= 1) s += __shfl_xor_sync(0xffffffffu, s, o);
    if ((threadIdx.x & 31) == 0) sm[threadIdx.x >> 5] = s;
    __syncthreads();
    if (threadIdx.x < 16) {
        float t = sm[threadIdx.x];
#pragma unroll
        for (int o = 8; o; o >>= 1) t += __shfl_xor_sync(0xffffu, t, o);
        if (threadIdx.x == 0) sm[0] = t;
    }
    __syncthreads();
    g_mb[(size_t)b * C_DIM * C_DIM + (size_t)c * C_DIM + threadIdx.x] =
        __float2bfloat16(v / (sm[0] + EPSV));
}

// ---------------- launch ------------------------------------------------------
extern "C" void kernel_launch(void* const* d_in, const int* in_sizes, int n_in,
                              void* d_out, int out_size) {
    const float* x  = (const float*)d_in[0];
    const float* wq = (const float*)d_in[1];
    const float* wk = (const float*)d_in[2];
    const float* wv = (const float*)d_in[3];
    const float* gamma = (const float*)d_in[4];
    float* out = (float*)d_out;

    void *p_xb, *p_xbt, *p_wb, *p_spart, *p_sb, *p_ab, *p_m, *p_mb, *p_mw;
    cudaGetSymbolAddress(&p_xb,  g_xb);
    cudaGetSymbolAddress(&p_xbt, g_xbt);
    cudaGetSymbolAddress(&p_wb,  g_wb);
    cudaGetSymbolAddress(&p_spart, g_spart);
    cudaGetSymbolAddress(&p_sb,  g_sb);
    cudaGetSymbolAddress(&p_ab,  g_ab);
    cudaGetSymbolAddress(&p_m,   g_m);
    cudaGetSymbolAddress(&p_mb,  g_mb);
    cudaGetSymbolAddress(&p_mw,  g_mw);

    cudaFuncSetAttribute(gemm_nt<0>, cudaFuncAttributeMaxDynamicSharedMemorySize, 2 * STG_BYTES);
    cudaFuncSetAttribute(gemm_nt<1>, cudaFuncAttributeMaxDynamicSharedMemorySize, 2 * STG_BYTES);
    cudaFuncSetAttribute(gemm_nt<3>, cudaFuncAttributeMaxDynamicSharedMemorySize, 2 * STG_BYTES);

    const long long CN = (long long)C_DIM * N_DIM;
    const long long CC = (long long)C_DIM * C_DIM;

    dim3 tb(32, 8);
    // 1) x -> bf16 (straight + transposed)
    cvt_x<<<dim3(N_DIM / 32, C_DIM / 32, BATCH), tb>>>(x);
    // 2) weights -> bf16 ([Wq;Wk] | Wv^T)
    cvt_w<<<(C_DIM * C_DIM + 255) / 256, 256>>>(wq, wk, wv);
    // 3) S partials = x @ x^T, split-K=4 (per-chunk K=1024)
    gemm_nt<0><<<dim3(C_DIM / BN, C_DIM / BM, BATCH * SKM), 256, 2 * STG_BYTES>>>(
        (const __nv_bfloat16*)p_xb, (const __nv_bfloat16*)p_xb, p_spart,
        C_DIM, N_DIM / SKM, N_DIM, N_DIM,
        CN, CN, CC, SKM, (long long)BATCH * CC, nullptr, nullptr);
    // 4) S = sum partials -> bf16
    sum_s<<<(int)(((size_t)BATCH * CC + 255) / 256), 256>>>();
    // 5) [Aq;Ak] = [Wq;Wk] @ S : M=1024, N=512, K=512 -> bf16 (S symmetric)
    gemm_nt<3><<<dim3(C_DIM / BN, 1024 / BM, BATCH), 256, 2 * STG_BYTES>>>(
        (const __nv_bfloat16*)p_wb, (const __nv_bfloat16*)p_sb, p_ab,
        C_DIM, C_DIM, C_DIM, C_DIM,
        0LL, CC, 2 * CC, 1, 0LL, nullptr, nullptr);
    // 6) norms: |Q_i|^2 = Aq_i . Wq_i ; |K_i|^2 = Ak_i . Wk_i
    norm_dots<<<dim3(2 * C_DIM / 8, BATCH), 256>>>();
    // 7) G = Aq @ Wk^T : M=512, N=512, K=512 -> fp32 g_m
    gemm_nt<0><<<dim3(C_DIM / BN, C_DIM / BM, BATCH), 256, 2 * STG_BYTES>>>(
        (const __nv_bfloat16*)p_ab, (const __nv_bfloat16*)p_wb + CC, p_m,
        C_DIM, C_DIM, C_DIM, C_DIM,
        2 * CC, 0LL, CC, 1, 0LL, nullptr, nullptr);
    // 8) column-wise: scale by 1/(|Q||K|), cosine softmax (in place)
    col_ops<<<dim3(C_DIM / 32, BATCH), dim3(32, 16)>>>();
    // 9) row-wise L1 normalize -> bf16
    row_ops<<<dim3(C_DIM, BATCH), 512>>>();
    // 10) MW = M @ Wv : M=512, N=512, K=512 -> bf16
    gemm_nt<3><<<dim3(C_DIM / BN, C_DIM / BM, BATCH), 256, 2 * STG_BYTES>>>(
        (const __nv_bfloat16*)p_mb, (const __nv_bfloat16*)p_wb + 2 * CC, p_mw,
        C_DIM, C_DIM, C_DIM, C_DIM,
        CC, 0LL, CC, 1, 0LL, nullptr, nullptr);
    // 11) out = x + gamma * (MW @ x) : M=512, N=4096, K=512
    gemm_nt<1><<<dim3(N_DIM / BN, C_DIM / BM, BATCH), 256, 2 * STG_BYTES>>>(
        (const __nv_bfloat16*)p_mw, (const __nv_bfloat16*)p_xbt, out,
        N_DIM, C_DIM, C_DIM, C_DIM,
        CC, CN, CN, 1, 0LL, x, gamma);
}